// round 5
// baseline (speedup 1.0000x reference)
#include <cuda_runtime.h>
#include <cuda_fp16.h>

// VectorQuantizer: z [32,4096,64] fp32, W [512,64] fp32.
// Out fp32: z_q_st (8388608) | indices-as-float (131072) | loss (1).
//
// R5: fp16 mma filter (4x tighter rigorous width than bf16) + deferred
// parallel exact rescore (candidate list, one chain per thread) + prep fused
// per-CTA. Candidate set provably contains the reference argmin; rescore uses
// the bitwise reference chain (verified rel_err==0.0 in R1-R4).

#define DIM       64
#define KCODES    512
#define NROWS     131072
#define ROWS_CTA  128
#define GRIDM     (NROWS / ROWS_CTA)     // 1024
#define THREADS   256
#define NELEM_ZQ  (NROWS * DIM)
#define SW_STRIDE 36                     // fp16-pair row stride: conflict-free
#define CAP       3072                   // candidate buffer entries

__device__ double g_part[GRIDM];

typedef unsigned int u32;
typedef unsigned long long u64;

__device__ __forceinline__ u32 fflip(float x) {
    u32 u = __float_as_uint(x);
    return (u & 0x80000000u) ? ~u : (u | 0x80000000u);
}
__device__ __forceinline__ float funflip(u32 u) {
    return (u & 0x80000000u) ? __uint_as_float(u ^ 0x80000000u)
                             : __uint_as_float(~u);
}

// exact reference distance chain: seq ascending-k fma, A+B-2C assembly
__device__ __forceinline__ float exact_dist(const float* __restrict__ zr,
                                            const float* __restrict__ wr,
                                            float zz, float wsq) {
    float acc = 0.0f;
    #pragma unroll
    for (int k = 0; k < DIM; k += 4) {
        float4 zv = *(const float4*)(zr + k);
        float4 wv = *(const float4*)(wr + k);
        acc = __fmaf_rn(zv.x, wv.x, acc);
        acc = __fmaf_rn(zv.y, wv.y, acc);
        acc = __fmaf_rn(zv.z, wv.z, acc);
        acc = __fmaf_rn(zv.w, wv.w, acc);
    }
    return __fsub_rn(__fadd_rn(zz, wsq), __fmul_rn(2.0f, acc));
}

__global__ __launch_bounds__(THREADS, 2)
void vq_main(const float* __restrict__ z, const float* __restrict__ W,
             float* __restrict__ out, int out_size) {
    extern __shared__ char smraw[];
    u64*    sbest = (u64*)smraw;                                  // 128*8
    double* sred  = (double*)(smraw + 1024);                      // 256*8
    u32*    sW    = (u32*)(smraw + 3072);                         // 512*36*4
    float*  swsq  = (float*)(smraw + 3072 + KCODES * SW_STRIDE * 4); // 512*4
    u32*    srmin = (u32*)(swsq + KCODES);                        // 128*4
    float*  sthr  = (float*)(srmin + ROWS_CTA);                   // 128*4
    float*  szz   = (float*)(sthr + ROWS_CTA);                    // 128*4
    u32*    scand = (u32*)(szz + ROWS_CTA);                       // CAP*4
    u32*    sctl  = (u32*)(scand + CAP);                          // cnt, ovf
    float*  swmax = (float*)(sctl + 2);

    const int tid  = threadIdx.x;
    const int lane = tid & 31;
    const int wid  = tid >> 5;
    const int gid  = lane >> 2;
    const int tig  = lane & 3;
    const int rowbase = blockIdx.x * ROWS_CTA;
    const float* zb = z + (size_t)rowbase * DIM;

    // ---- stage W -> fp16 pairs (conflict-free padded layout) ----
    for (int i = tid; i < KCODES * (DIM / 2); i += THREADS) {
        int j = i >> 5, kw = i & 31;
        float2 g = ((const float2*)W)[i];
        __half2 h = __float22half2_rn(g);          // lo = g.x = W[j][2kw]
        sW[j * SW_STRIDE + kw] = *(u32*)&h;
    }
    // ---- wsq: exact sequential chain per code (2 codes per thread) ----
    for (int j = tid; j < KCODES; j += THREADS) {
        const float* w = W + j * DIM;
        float acc = 0.0f;
        #pragma unroll
        for (int k = 0; k < DIM; k++)
            acc = __fadd_rn(acc, __fmul_rn(w[k], w[k]));
        swsq[j] = acc;
    }
    if (tid < ROWS_CTA) { srmin[tid] = 0xFFFFFFFFu; sbest[tid] = ~0ull; }
    if (tid == 0) { sctl[0] = 0; sctl[1] = 0; }
    __syncthreads();

    // ---- wmax = max_j ||w_j|| (scratch in scand, free until pass 2) ----
    {
        float* scratch = (float*)scand;
        scratch[tid] = fmaxf(sqrtf(swsq[tid]), sqrtf(swsq[tid + 256]));
        __syncthreads();
        #pragma unroll
        for (int s = 128; s > 0; s >>= 1) {
            if (tid < s) scratch[tid] = fmaxf(scratch[tid], scratch[tid + s]);
            __syncthreads();
        }
        if (tid == 0) *swmax = scratch[0] * 1.0001f;
        __syncthreads();
    }

    // ---- A fragments (rows m0, m0+8) fp16, straight from global z ----
    const int m0 = wid * 16 + gid;
    u32 A[4][4];
    #pragma unroll
    for (int kk = 0; kk < 4; kk++) {
        int kb = kk * 16;
        float2 p0 = __ldg((const float2*)(zb + m0 * DIM + kb + tig * 2));
        float2 p1 = __ldg((const float2*)(zb + (m0 + 8) * DIM + kb + tig * 2));
        float2 p2 = __ldg((const float2*)(zb + m0 * DIM + kb + 8 + tig * 2));
        float2 p3 = __ldg((const float2*)(zb + (m0 + 8) * DIM + kb + 8 + tig * 2));
        __half2 h;
        h = __float22half2_rn(p0); A[kk][0] = *(u32*)&h;
        h = __float22half2_rn(p1); A[kk][1] = *(u32*)&h;
        h = __float22half2_rn(p2); A[kk][2] = *(u32*)&h;
        h = __float22half2_rn(p3); A[kk][3] = *(u32*)&h;
    }

    // ---- exact zz per row (sequential chain) ----
    if (tid < ROWS_CTA) {
        const float* zr = zb + tid * DIM;
        float acc = 0.0f;
        #pragma unroll
        for (int k = 0; k < DIM; k += 4) {
            float4 v = *(const float4*)(zr + k);
            acc = __fadd_rn(acc, __fmul_rn(v.x, v.x));
            acc = __fadd_rn(acc, __fmul_rn(v.y, v.y));
            acc = __fadd_rn(acc, __fmul_rn(v.z, v.z));
            acc = __fadd_rn(acc, __fmul_rn(v.w, v.w));
        }
        szz[tid] = acc;
    }

    // ================= PASS 1: per-row filter minimum =================
    {
        float rmin0 = 3.0e38f, rmin1 = 3.0e38f;
        #pragma unroll 1
        for (int n0 = 0; n0 < KCODES / 8; n0++) {
            const int j0 = n0 * 8;
            float c0 = 0.f, c1 = 0.f, c2 = 0.f, c3 = 0.f;
            const u32* wrow = sW + (j0 + gid) * SW_STRIDE + tig;
            #pragma unroll
            for (int kk = 0; kk < 4; kk++) {
                u32 b0 = wrow[kk * 8];
                u32 b1 = wrow[kk * 8 + 4];
                asm volatile(
                    "mma.sync.aligned.m16n8k16.row.col.f32.f16.f16.f32 "
                    "{%0,%1,%2,%3}, {%4,%5,%6,%7}, {%8,%9}, {%0,%1,%2,%3};"
                    : "+f"(c0), "+f"(c1), "+f"(c2), "+f"(c3)
                    : "r"(A[kk][0]), "r"(A[kk][1]), "r"(A[kk][2]), "r"(A[kk][3]),
                      "r"(b0), "r"(b1));
            }
            const int jc = j0 + tig * 2;
            float w0 = swsq[jc], w1 = swsq[jc + 1];
            rmin0 = fminf(rmin0, fminf(__fsub_rn(w0, __fmul_rn(2.0f, c0)),
                                       __fsub_rn(w1, __fmul_rn(2.0f, c1))));
            rmin1 = fminf(rmin1, fminf(__fsub_rn(w0, __fmul_rn(2.0f, c2)),
                                       __fsub_rn(w1, __fmul_rn(2.0f, c3))));
        }
        atomicMin(&srmin[m0], fflip(rmin0));
        atomicMin(&srmin[m0 + 8], fflip(rmin1));
    }
    __syncthreads();

    // ---- rigorous threshold: fp16-rne + subnormal + accum + assembly ----
    if (tid < ROWS_CTA) {
        float znorm = sqrtf(szz[tid]) * 1.0001f;
        float width = 4.1e-3f * znorm * (*swmax) + 1.1e-6f * znorm + 4.0e-5f;
        sthr[tid] = funflip(srmin[tid]) + width;
    }
    __syncthreads();

    // ================= PASS 2: record candidates =================
    {
        const float thr_a = sthr[m0];
        const float thr_b = sthr[m0 + 8];
        #pragma unroll 1
        for (int n0 = 0; n0 < KCODES / 8; n0++) {
            const int j0 = n0 * 8;
            float c0 = 0.f, c1 = 0.f, c2 = 0.f, c3 = 0.f;
            const u32* wrow = sW + (j0 + gid) * SW_STRIDE + tig;
            #pragma unroll
            for (int kk = 0; kk < 4; kk++) {
                u32 b0 = wrow[kk * 8];
                u32 b1 = wrow[kk * 8 + 4];
                asm volatile(
                    "mma.sync.aligned.m16n8k16.row.col.f32.f16.f16.f32 "
                    "{%0,%1,%2,%3}, {%4,%5,%6,%7}, {%8,%9}, {%0,%1,%2,%3};"
                    : "+f"(c0), "+f"(c1), "+f"(c2), "+f"(c3)
                    : "r"(A[kk][0]), "r"(A[kk][1]), "r"(A[kk][2]), "r"(A[kk][3]),
                      "r"(b0), "r"(b1));
            }
            const int jc = j0 + tig * 2;
            float w0 = swsq[jc], w1 = swsq[jc + 1];
            float s0 = __fsub_rn(w0, __fmul_rn(2.0f, c0));
            float s1 = __fsub_rn(w1, __fmul_rn(2.0f, c1));
            float s2 = __fsub_rn(w0, __fmul_rn(2.0f, c2));
            float s3 = __fsub_rn(w1, __fmul_rn(2.0f, c3));
            #pragma unroll
            for (int q = 0; q < 4; q++) {
                float s   = (q == 0) ? s0 : (q == 1) ? s1 : (q == 2) ? s2 : s3;
                float thr = (q < 2) ? thr_a : thr_b;
                int   r   = (q < 2) ? m0 : m0 + 8;
                int   j   = jc + (q & 1);
                if (s <= thr) {
                    u32 idx = atomicAdd(&sctl[0], 1u);
                    if (idx < CAP) scand[idx] = ((u32)r << 9) | (u32)j;
                    else           sctl[1] = 1;
                }
            }
        }
    }
    __syncthreads();

    // ================= deferred exact rescore =================
    if (sctl[1] == 0) {
        int n = min(sctl[0], (u32)CAP);
        for (int c = tid; c < n; c += THREADS) {
            u32 e = scand[c];
            int r = e >> 9, j = e & 511;
            float dist = exact_dist(zb + r * DIM, W + j * DIM, szz[r], swsq[j]);
            u64 pk = ((u64)fflip(dist) << 32) | (u32)j;
            atomicMin(&sbest[r], pk);
        }
    } else {
        // overflow fallback (statistically unreachable): full exact scan
        for (int r = wid; r < ROWS_CTA; r += 8) {
            u64 best = ~0ull;
            for (int j = lane; j < KCODES; j += 32) {
                float dist = exact_dist(zb + r * DIM, W + j * DIM, szz[r], swsq[j]);
                u64 pk = ((u64)fflip(dist) << 32) | (u32)j;
                best = min(best, pk);
            }
            #pragma unroll
            for (int off = 16; off > 0; off >>= 1)
                best = min(best, __shfl_xor_sync(0xFFFFFFFFu, best, off));
            if (lane == 0) atomicMin(&sbest[r], best);
        }
    }
    __syncthreads();

    // ================= epilogue: z_q_st, indices, loss =================
    float lsum = 0.0f;
    if (tid < ROWS_CTA) {
        const int r = tid;
        const int grow = rowbase + r;
        const int bj = (int)(sbest[r] & 0xFFFFFFFFull);
        const float* zr = zb + r * DIM;
        const float* wr = W + bj * DIM;
        #pragma unroll
        for (int k = 0; k < DIM; k += 4) {
            float4 zv = *(const float4*)(zr + k);
            float4 wv = *(const float4*)(wr + k);
            float4 o; float df;
            o.x = __fadd_rn(zv.x, __fsub_rn(wv.x, zv.x));
            df = __fsub_rn(zv.x, o.x); lsum = __fadd_rn(lsum, __fmul_rn(df, df));
            o.y = __fadd_rn(zv.y, __fsub_rn(wv.y, zv.y));
            df = __fsub_rn(zv.y, o.y); lsum = __fadd_rn(lsum, __fmul_rn(df, df));
            o.z = __fadd_rn(zv.z, __fsub_rn(wv.z, zv.z));
            df = __fsub_rn(zv.z, o.z); lsum = __fadd_rn(lsum, __fmul_rn(df, df));
            o.w = __fadd_rn(zv.w, __fsub_rn(wv.w, zv.w));
            df = __fsub_rn(zv.w, o.w); lsum = __fadd_rn(lsum, __fmul_rn(df, df));
            *(float4*)(out + (size_t)grow * DIM + k) = o;
        }
        if (out_size > NELEM_ZQ + grow)
            out[NELEM_ZQ + grow] = (float)bj;
    }
    sred[tid] = (double)lsum;
    __syncthreads();
    #pragma unroll
    for (int s = THREADS / 2; s > 0; s >>= 1) {
        if (tid < s) sred[tid] += sred[tid + s];
        __syncthreads();
    }
    if (tid == 0) g_part[blockIdx.x] = sred[0];
}

// ---------------------------------------------------------------------------
__global__ void loss_kernel(float* __restrict__ out, int out_size) {
    __shared__ double red[GRIDM];
    red[threadIdx.x] = g_part[threadIdx.x];
    __syncthreads();
    #pragma unroll
    for (int s = GRIDM / 2; s > 0; s >>= 1) {
        if (threadIdx.x < s) red[threadIdx.x] += red[threadIdx.x + s];
        __syncthreads();
    }
    if (threadIdx.x == 0) {
        float loss = (float)(0.25 * red[0] / (double)((size_t)NROWS * DIM));
        int loss_pos = NELEM_ZQ + NROWS;
        if (out_size > loss_pos) out[loss_pos] = loss;
    }
}

extern "C" void kernel_launch(void* const* d_in, const int* in_sizes, int n_in,
                              void* d_out, int out_size) {
    const float* z = (const float*)d_in[0];
    const float* W = (const float*)d_in[1];
    float* out = (float*)d_out;

    size_t smem = 3072
                + (size_t)KCODES * SW_STRIDE * 4   // W fp16 padded
                + KCODES * 4                       // wsq
                + ROWS_CTA * 4 * 3                 // rmin, thr, zz
                + (size_t)CAP * 4 + 16;            // candidates + ctl + wmax
    static bool attr_set = false;
    if (!attr_set) {
        cudaFuncSetAttribute(vq_main, cudaFuncAttributeMaxDynamicSharedMemorySize,
                             (int)smem);
        attr_set = true;
    }

    vq_main<<<GRIDM, THREADS, smem>>>(z, W, out, out_size);
    loss_kernel<<<1, GRIDM>>>(out, out_size);
}

// round 6
// speedup vs baseline: 1.3052x; 1.3052x over previous
#include <cuda_runtime.h>
#include <cuda_fp16.h>

// VectorQuantizer: z [32,4096,64] fp32, W [512,64] fp32.
// Out fp32: z_q_st (8388608) | indices-as-float (131072) | loss (1).
//
// R6: single-pass fp16 mma filter with running-min threshold (provably
// superset of the width-window candidates), z staged in padded smem,
// parallel prep kernel, coalesced linear epilogue, deferred exact rescore
// with the bitwise reference chain (rel_err==0.0 in R1-R5).

#define DIM       64
#define KCODES    512
#define NROWS     131072
#define ROWS_CTA  256
#define GRIDM     (NROWS / ROWS_CTA)     // 512
#define THREADS   512
#define NELEM_ZQ  (NROWS * DIM)
#define SZ_STRIDE 66                     // fp32 z row stride (words)
#define SW_STRIDE 36                     // fp16-pair row stride (words)
#define CAP       4096                   // candidate entries

__device__ double       g_part[GRIDM];
__device__ unsigned int g_Wh[KCODES * (DIM / 2)];   // fp16x2 codebook
__device__ float        g_wsq[KCODES];
__device__ unsigned int g_wmax_bits;                 // fflip-encoded max ||w||

typedef unsigned int u32;
typedef unsigned long long u64;

__device__ __forceinline__ u32 fflip(float x) {
    u32 u = __float_as_uint(x);
    return (u & 0x80000000u) ? ~u : (u | 0x80000000u);
}
__device__ __forceinline__ float funflip(u32 u) {
    return (u & 0x80000000u) ? __uint_as_float(u ^ 0x80000000u)
                             : __uint_as_float(~u);
}

// ---------------------------------------------------------------------------
// Prep: wsq (exact sequential chain), W->fp16 (coalesced), wmax (atomicMax)
// ---------------------------------------------------------------------------
__global__ void prep_kernel(const float* __restrict__ W) {
    const int j = blockIdx.x * 64 + threadIdx.x;     // 8 blocks x 64 thr = 512
    const int gtid = j;

    // coalesced fp16 conversion (512 threads grid-wide, 32 iters each)
    for (int i = gtid; i < KCODES * (DIM / 2); i += 512) {
        float2 g = ((const float2*)W)[i];
        __half2 h = __float22half2_rn(g);
        g_Wh[i] = *(u32*)&h;
    }

    // exact wsq chain for code j
    const float* w = W + j * DIM;
    float acc = 0.0f;
    #pragma unroll
    for (int k = 0; k < DIM; k++)
        acc = __fadd_rn(acc, __fmul_rn(w[k], w[k]));
    g_wsq[j] = acc;

    // block max of ||w||, then deterministic global atomicMax
    __shared__ float red[64];
    red[threadIdx.x] = sqrtf(acc);
    __syncthreads();
    #pragma unroll
    for (int s = 32; s > 0; s >>= 1) {
        if (threadIdx.x < s) red[threadIdx.x] = fmaxf(red[threadIdx.x], red[threadIdx.x + s]);
        __syncthreads();
    }
    if (threadIdx.x == 0) atomicMax(&g_wmax_bits, fflip(red[0]));
}

// ---------------------------------------------------------------------------
// Main
// ---------------------------------------------------------------------------
__global__ __launch_bounds__(THREADS, 1)
void vq_main(const float* __restrict__ z, const float* __restrict__ W,
             float* __restrict__ out, int out_size) {
    extern __shared__ char smraw[];
    u64*    sbest = (u64*)smraw;                                   // 256*8
    double* sred  = (double*)(smraw + 2048);                       // 512*8
    float*  sz    = (float*)(smraw + 6144);                        // 256*66*4
    u32*    sW    = (u32*)(smraw + 6144 + ROWS_CTA * SZ_STRIDE * 4);
    float*  swsq  = (float*)((char*)sW + KCODES * SW_STRIDE * 4);  // 512*4
    float*  szz   = swsq + KCODES;                                 // 256*4
    float*  swid  = szz + ROWS_CTA;                                // 256*4
    u32*    scand = (u32*)(swid + ROWS_CTA);                       // CAP*4
    u32*    sctl  = scand + CAP;                                   // cnt, ovf

    const int tid  = threadIdx.x;
    const int lane = tid & 31;
    const int wid  = tid >> 5;
    const int gid  = lane >> 2;
    const int tig  = lane & 3;
    const int rowbase = blockIdx.x * ROWS_CTA;
    const float wmax = funflip(g_wmax_bits) * 1.0001f;

    // ---- stage z (coalesced float2 -> padded smem) ----
    const float2* zg = (const float2*)(z + (size_t)rowbase * DIM);
    for (int i = tid; i < ROWS_CTA * (DIM / 2); i += THREADS) {
        int r = i >> 5, c2 = i & 31;
        *(float2*)(sz + r * SZ_STRIDE + c2 * 2) = zg[i];
    }
    // ---- stage fp16 W (coalesced read, padded smem) ----
    for (int i = tid; i < KCODES * (DIM / 2); i += THREADS) {
        int j = i >> 5, kw = i & 31;
        sW[j * SW_STRIDE + kw] = g_Wh[i];
    }
    for (int i = tid; i < KCODES; i += THREADS) swsq[i] = g_wsq[i];
    if (tid < ROWS_CTA) sbest[tid] = ~0ull;
    if (tid == 0) { sctl[0] = 0; sctl[1] = 0; }
    __syncthreads();

    // ---- exact zz per row (sequential chain, from smem) + width ----
    if (tid < ROWS_CTA) {
        const float* zr = sz + tid * SZ_STRIDE;
        float acc = 0.0f;
        #pragma unroll
        for (int k = 0; k < DIM; k++)
            acc = __fadd_rn(acc, __fmul_rn(zr[k], zr[k]));
        szz[tid] = acc;
        float znorm = sqrtf(acc) * 1.0001f;
        swid[tid] = 4.1e-3f * znorm * wmax + 1.1e-6f * znorm + 4.0e-5f;
    }
    __syncthreads();

    // ---- A fragments (rows m0, m0+8) fp16 from smem ----
    const int m0 = wid * 16 + gid;
    u32 A[4][4];
    #pragma unroll
    for (int kk = 0; kk < 4; kk++) {
        int kb = kk * 16;
        float2 p0 = *(float2*)(sz + m0 * SZ_STRIDE + kb + tig * 2);
        float2 p1 = *(float2*)(sz + (m0 + 8) * SZ_STRIDE + kb + tig * 2);
        float2 p2 = *(float2*)(sz + m0 * SZ_STRIDE + kb + 8 + tig * 2);
        float2 p3 = *(float2*)(sz + (m0 + 8) * SZ_STRIDE + kb + 8 + tig * 2);
        __half2 h;
        h = __float22half2_rn(p0); A[kk][0] = *(u32*)&h;
        h = __float22half2_rn(p1); A[kk][1] = *(u32*)&h;
        h = __float22half2_rn(p2); A[kk][2] = *(u32*)&h;
        h = __float22half2_rn(p3); A[kk][3] = *(u32*)&h;
    }

    // ============ single-pass filter: running min + record ============
    {
        const float widA = swid[m0], widB = swid[m0 + 8];
        float rminA = 3.0e38f, rminB = 3.0e38f;

        #pragma unroll 1
        for (int n0 = 0; n0 < KCODES / 8; n0++) {
            const int j0 = n0 * 8;
            float c0 = 0.f, c1 = 0.f, c2 = 0.f, c3 = 0.f;
            const u32* wrow = sW + (j0 + gid) * SW_STRIDE + tig;
            #pragma unroll
            for (int kk = 0; kk < 4; kk++) {
                u32 b0 = wrow[kk * 8];
                u32 b1 = wrow[kk * 8 + 4];
                asm volatile(
                    "mma.sync.aligned.m16n8k16.row.col.f32.f16.f16.f32 "
                    "{%0,%1,%2,%3}, {%4,%5,%6,%7}, {%8,%9}, {%0,%1,%2,%3};"
                    : "+f"(c0), "+f"(c1), "+f"(c2), "+f"(c3)
                    : "r"(A[kk][0]), "r"(A[kk][1]), "r"(A[kk][2]), "r"(A[kk][3]),
                      "r"(b0), "r"(b1));
            }
            const int jc = j0 + tig * 2;
            float w0 = swsq[jc], w1 = swsq[jc + 1];
            float s0 = __fsub_rn(w0, __fmul_rn(2.0f, c0));
            float s1 = __fsub_rn(w1, __fmul_rn(2.0f, c1));
            float s2 = __fsub_rn(w0, __fmul_rn(2.0f, c2));
            float s3 = __fsub_rn(w1, __fmul_rn(2.0f, c3));

            // row-min of this 8-code block across the 4 tig lanes
            float mA = fminf(s0, s1);
            mA = fminf(mA, __shfl_xor_sync(0xFFFFFFFFu, mA, 1));
            mA = fminf(mA, __shfl_xor_sync(0xFFFFFFFFu, mA, 2));
            float mB = fminf(s2, s3);
            mB = fminf(mB, __shfl_xor_sync(0xFFFFFFFFu, mB, 1));
            mB = fminf(mB, __shfl_xor_sync(0xFFFFFFFFu, mB, 2));
            rminA = fminf(rminA, mA);
            rminB = fminf(rminB, mB);

            // record: running_min >= final_min, so threshold is a superset
            const float tA = rminA + widA, tB = rminB + widB;
            if (s0 <= tA) { u32 x = atomicAdd(&sctl[0], 1u);
                            if (x < CAP) scand[x] = ((u32)m0 << 9) | (u32)jc; else sctl[1] = 1; }
            if (s1 <= tA) { u32 x = atomicAdd(&sctl[0], 1u);
                            if (x < CAP) scand[x] = ((u32)m0 << 9) | (u32)(jc + 1); else sctl[1] = 1; }
            if (s2 <= tB) { u32 x = atomicAdd(&sctl[0], 1u);
                            if (x < CAP) scand[x] = ((u32)(m0 + 8) << 9) | (u32)jc; else sctl[1] = 1; }
            if (s3 <= tB) { u32 x = atomicAdd(&sctl[0], 1u);
                            if (x < CAP) scand[x] = ((u32)(m0 + 8) << 9) | (u32)(jc + 1); else sctl[1] = 1; }
        }
    }
    __syncthreads();

    // ============ deferred exact rescore (bitwise reference chain) ============
    if (sctl[1] == 0) {
        int n = min(sctl[0], (u32)CAP);
        for (int c = tid; c < n; c += THREADS) {
            u32 e = scand[c];
            int r = e >> 9, j = e & 511;
            const float* zr = sz + r * SZ_STRIDE;
            const float* wr = W + j * DIM;
            float acc = 0.0f;
            #pragma unroll
            for (int k = 0; k < DIM; k += 4) {
                float2 za = *(const float2*)(zr + k);
                float2 zb = *(const float2*)(zr + k + 2);
                float4 wv = *(const float4*)(wr + k);
                acc = __fmaf_rn(za.x, wv.x, acc);
                acc = __fmaf_rn(za.y, wv.y, acc);
                acc = __fmaf_rn(zb.x, wv.z, acc);
                acc = __fmaf_rn(zb.y, wv.w, acc);
            }
            float dist = __fsub_rn(__fadd_rn(szz[r], swsq[j]), __fmul_rn(2.0f, acc));
            atomicMin(&sbest[r], ((u64)fflip(dist) << 32) | (u32)j);
        }
    } else {
        // overflow fallback: warp-cooperative full exact scan (always correct)
        for (int r = wid; r < ROWS_CTA; r += THREADS / 32) {
            const float* zr = sz + r * SZ_STRIDE;
            u64 best = ~0ull;
            for (int j = lane; j < KCODES; j += 32) {
                const float* wr = W + j * DIM;
                float acc = 0.0f;
                #pragma unroll
                for (int k = 0; k < DIM; k += 4) {
                    float2 za = *(const float2*)(zr + k);
                    float2 zb = *(const float2*)(zr + k + 2);
                    float4 wv = *(const float4*)(wr + k);
                    acc = __fmaf_rn(za.x, wv.x, acc);
                    acc = __fmaf_rn(za.y, wv.y, acc);
                    acc = __fmaf_rn(zb.x, wv.z, acc);
                    acc = __fmaf_rn(zb.y, wv.w, acc);
                }
                float dist = __fsub_rn(__fadd_rn(szz[r], swsq[j]), __fmul_rn(2.0f, acc));
                best = min(best, ((u64)fflip(dist) << 32) | (u32)j);
            }
            #pragma unroll
            for (int off = 16; off > 0; off >>= 1)
                best = min(best, __shfl_xor_sync(0xFFFFFFFFu, best, off));
            if (lane == 0) atomicMin(&sbest[r], best);
        }
    }
    __syncthreads();

    // ============ epilogue: coalesced linear z_q_st + loss ============
    double dsum = 0.0;
    for (int i = tid; i < ROWS_CTA * DIM; i += THREADS) {
        int r = i >> 6, k = i & 63;
        int bj = (int)(sbest[r] & 0xFFFFFFFFull);
        float zv = sz[r * SZ_STRIDE + k];
        float wv = __ldg(W + bj * DIM + k);
        float st = __fadd_rn(zv, __fsub_rn(wv, zv));
        float df = __fsub_rn(zv, st);
        dsum += (double)__fmul_rn(df, df);
        out[(size_t)rowbase * DIM + i] = st;
    }
    if (tid < ROWS_CTA)
        out[NELEM_ZQ + rowbase + tid] = (float)(sbest[tid] & 0xFFFFFFFFull);

    sred[tid] = dsum;
    __syncthreads();
    #pragma unroll
    for (int s = THREADS / 2; s > 0; s >>= 1) {
        if (tid < s) sred[tid] += sred[tid + s];
        __syncthreads();
    }
    if (tid == 0) g_part[blockIdx.x] = sred[0];
}

// ---------------------------------------------------------------------------
__global__ void loss_kernel(float* __restrict__ out, int out_size) {
    __shared__ double red[GRIDM];
    red[threadIdx.x] = g_part[threadIdx.x];
    __syncthreads();
    #pragma unroll
    for (int s = GRIDM / 2; s > 0; s >>= 1) {
        if (threadIdx.x < s) red[threadIdx.x] += red[threadIdx.x + s];
        __syncthreads();
    }
    if (threadIdx.x == 0) {
        float loss = (float)(0.25 * red[0] / (double)((size_t)NROWS * DIM));
        int loss_pos = NELEM_ZQ + NROWS;
        if (out_size > loss_pos) out[loss_pos] = loss;
    }
}

extern "C" void kernel_launch(void* const* d_in, const int* in_sizes, int n_in,
                              void* d_out, int out_size) {
    const float* z = (const float*)d_in[0];
    const float* W = (const float*)d_in[1];
    float* out = (float*)d_out;

    size_t smem = 6144
                + (size_t)ROWS_CTA * SZ_STRIDE * 4   // z
                + (size_t)KCODES * SW_STRIDE * 4     // W fp16
                + KCODES * 4                         // wsq
                + ROWS_CTA * 4 * 2                   // zz, width
                + (size_t)CAP * 4 + 16;              // candidates + ctl
    static bool attr_set = false;
    if (!attr_set) {
        cudaFuncSetAttribute(vq_main, cudaFuncAttributeMaxDynamicSharedMemorySize,
                             (int)smem);
        attr_set = true;
    }

    prep_kernel<<<8, 64>>>(W);
    vq_main<<<GRIDM, THREADS, smem>>>(z, W, out, out_size);
    loss_kernel<<<1, GRIDM>>>(out, out_size);
}